// round 16
// baseline (speedup 1.0000x reference)
#include <cuda_runtime.h>
#include <cuda_fp16.h>

#define NN 4096
#define FF 128
#define EE 64
#define MAXD 192
#define LRALPHA 0.2f
#define FULLW 0xffffffffu

// ---- scratch (device globals) ----
__device__ float  g_wa[6][FF];
__device__ float  g_sv[6][NN];          // s1_fwd, u_fwd, s1_bwd, u_bwd, s1_geo, u_geo
__device__ float  g_s2[3][NN];
__device__ int    g_cnt[3][NN];
__device__ int    g_rowlist[3][NN * MAXD];
__device__ int    g_colcnt[NN];
__device__ float4 g_collist4[NN * MAXD]; // CSC entries: {s1_i, m_i, 1/Z_i, bitcast(i)}
__device__ __half g_yth[NN * EE];        // fp16 copy of (weight @ t^T), [n][e]

__device__ __forceinline__ float lrelu(float x) {
    return x > 0.f ? x : LRALPHA * x;
}

// ---- A0: wa[k] = W @ a only (1 block, 128 threads; colcnt zero moved to sB) ----
__global__ void wa_kernel(const float* __restrict__ Wf, const float* __restrict__ af1, const float* __restrict__ af2,
                          const float* __restrict__ Wb, const float* __restrict__ ab1, const float* __restrict__ ab2,
                          const float* __restrict__ Wg, const float* __restrict__ ag1, const float* __restrict__ ag2) {
    int tid = threadIdx.x;            // 128
    for (int i = tid; i < 6 * FF; i += 128) {
        int k = i >> 7;
        int f = i & 127;
        const float* W = (k < 2) ? Wf : (k < 4) ? Wb : Wg;
        const float* a = (k == 0) ? af1 : (k == 1) ? af2 : (k == 2) ? ab1 :
                         (k == 3) ? ab2 : (k == 4) ? ag1 : ag2;
        float s = 0.f;
#pragma unroll
        for (int e = 0; e < EE; e++) s += W[f * EE + e] * a[e];
        g_wa[k][f] = s;
    }
}

// ---- sB: zero backward column counters (hides under scan; only csc/agg_bwd touch it) ----
__global__ void zero_colcnt_kernel() {
    g_colcnt[blockIdx.x * 256 + threadIdx.x] = 0;
}

// ---- A1: sv[k][n] = t[n,:] . wa[k]; warp per row; interleaved reductions ----
__global__ void proj_sv_kernel(const float* __restrict__ t) {
    __shared__ float swa[6][FF];
    int tid = threadIdx.x;            // 256
    for (int i = tid; i < 6 * FF; i += 256)
        ((float*)swa)[i] = ((const float*)g_wa)[i];
    __syncthreads();
    int wid = tid >> 5, lane = tid & 31;
    int row = blockIdx.x * 8 + wid;
    const float4* t4 = reinterpret_cast<const float4*>(t + (size_t)row * FF);
    float4 v = __ldg(t4 + lane);
    float acc[6];
#pragma unroll
    for (int k = 0; k < 6; k++) {
        float4 w = reinterpret_cast<const float4*>(swa[k])[lane];
        acc[k] = v.x * w.x + v.y * w.y + v.z * w.z + v.w * w.w;
    }
    // stage-interleaved tree reductions: 6 independent chains overlap in the pipe
#pragma unroll
    for (int o = 16; o; o >>= 1) {
#pragma unroll
        for (int k = 0; k < 6; k++)
            acc[k] += __shfl_xor_sync(FULLW, acc[k], o);
    }
    if (lane == 0) {
#pragma unroll
        for (int k = 0; k < 6; k++) g_sv[k][row] = acc[k];
    }
}

// ---- B-head: y = weight @ t^T -> out part 0 + fp16 table ----
__global__ void y_kernel(const float* __restrict__ t,
                         const float* __restrict__ weight,
                         float* __restrict__ out) {
    int n0 = blockIdx.x * 32;
    __shared__ float Gs[FF][32];
    __shared__ float Ws[EE][FF];
    __shared__ __align__(16) __half Hs[32][EE];

    int tid = threadIdx.y * 32 + threadIdx.x;   // 256
    for (int i = tid; i < 32 * FF; i += 256) {
        int nn = i & 31;
        int f = i >> 5;
        Gs[f][nn] = t[(size_t)(n0 + nn) * FF + f];
    }
    for (int i = tid; i < EE * FF; i += 256)
        Ws[i / FF][i % FF] = weight[i];
    __syncthreads();

    int tx = threadIdx.x;
    int ty = threadIdx.y;
    float acc[8] = {0.f, 0.f, 0.f, 0.f, 0.f, 0.f, 0.f, 0.f};
    for (int f = 0; f < FF; f++) {
        float gv = Gs[f][tx];
#pragma unroll
        for (int eg = 0; eg < 8; eg++)
            acc[eg] += Ws[ty * 8 + eg][f] * gv;
    }
#pragma unroll
    for (int eg = 0; eg < 8; eg++) {
        int e = ty * 8 + eg;
        out[(size_t)e * NN + n0 + tx] = acc[eg];
        Hs[tx][e] = __float2half_rn(acc[eg]);
    }
    __syncthreads();
    {
        int nn = tid >> 3;
        int ch = tid & 7;
        reinterpret_cast<uint4*>(&g_yth[(size_t)(n0 + nn) * EE])[ch] =
            reinterpret_cast<const uint4*>(Hs[nn])[ch];
    }
}

// ---- A2: adjacency scan with inline dot. 128 thr/row, 8 uint4, streaming loads. ----
__global__ void scan_kernel(const float* __restrict__ fwd,
                            const float* __restrict__ bwd,
                            const float* __restrict__ geo) {
    int a = blockIdx.y;
    int row = blockIdx.x;
    const float* adj = (a == 0) ? fwd : (a == 1) ? bwd : geo;
    const uint4* rp = reinterpret_cast<const uint4*>(adj + (size_t)row * NN);

    __shared__ int scnt;
    __shared__ float sdot;
    if (threadIdx.x == 0) { scnt = 0; sdot = 0.f; }
    __syncthreads();

    const float* u = g_sv[2 * a + 1];
    int* list = &g_rowlist[a][(size_t)row * MAXD];
    int t = threadIdx.x;              // 0..127
    int lane = t & 31;

    uint4 v[8];
#pragma unroll
    for (int k = 0; k < 8; k++) v[k] = __ldcs(rp + t + k * 128);   // evict-first

    // 1.0f = 0x3F800000 -> (>>29)&1 == 1 ; 0.0f -> 0
    unsigned mask = 0;
#pragma unroll
    for (int k = 0; k < 8; k++) {
        mask |= ((v[k].x >> 29) & 1u) << (4 * k + 0);
        mask |= ((v[k].y >> 29) & 1u) << (4 * k + 1);
        mask |= ((v[k].z >> 29) & 1u) << (4 * k + 2);
        mask |= ((v[k].w >> 29) & 1u) << (4 * k + 3);
    }

    int cnt = __popc(mask);
    int incl = cnt;
#pragma unroll
    for (int d = 1; d < 32; d <<= 1) {
        int nb = __shfl_up_sync(FULLW, incl, d);
        if (lane >= d) incl += nb;
    }
    int warpTotal = __shfl_sync(FULLW, incl, 31);
    int excl = incl - cnt;
    int wb = 0;
    if (lane == 0 && warpTotal) wb = atomicAdd(&scnt, warpTotal);
    wb = __shfl_sync(FULLW, wb, 0);
    int base = wb + excl;

    float dot = 0.f;
    unsigned m = mask;
    while (m) {
        int b = __ffs(m) - 1;
        m &= m - 1;
        int col = (t << 2) + ((b >> 2) << 9) + (b & 3);
        if (base < MAXD) list[base] = col;
        base++;
        dot += u[col];
    }

#pragma unroll
    for (int o = 16; o; o >>= 1) dot += __shfl_xor_sync(FULLW, dot, o);
    if (lane == 0) atomicAdd(&sdot, dot);
    __syncthreads();

    if (threadIdx.x == 0) {
        int c = scnt;
        g_cnt[a][row] = min(c, MAXD);
        float deg = (c < 1) ? 1.f : (float)c;
        g_s2[a][row] = sdot / deg;
    }
}

// ---- B0: fused bwd softmax stats + CSC scatter — 2 warps per row. ----
__global__ void csc_stats_kernel() {
    int tid = threadIdx.x;            // 256
    int wid = tid >> 5, lane = tid & 31;
    int rloc = wid >> 1;
    int sub = wid & 1;
    int row = blockIdx.x * 4 + rloc;

    __shared__ float sm[4][2];
    __shared__ float sz[4][2];

    int c = g_cnt[1][row];
    const int* list = &g_rowlist[1][(size_t)row * MAXD];
    float s1 = g_sv[2][row];
    const float* s2 = g_s2[1];

    float vals[3];
    int cols[3];
    float mx = -3.0e38f;
#pragma unroll
    for (int k = 0; k < 3; k++) {
        int j = sub * 96 + k * 32 + lane;
        if (j < c) {
            int col = list[j];
            cols[k] = col;
            float x = lrelu(s1 + s2[col]);
            vals[k] = x;
            mx = fmaxf(mx, x);
        } else vals[k] = -3.0e38f;
    }
#pragma unroll
    for (int o = 16; o; o >>= 1) mx = fmaxf(mx, __shfl_xor_sync(FULLW, mx, o));
    if (lane == 0) sm[rloc][sub] = mx;
    __syncthreads();
    mx = fmaxf(sm[rloc][0], sm[rloc][1]);

    float z = 0.f;
#pragma unroll
    for (int k = 0; k < 3; k++) {
        int j = sub * 96 + k * 32 + lane;
        if (j < c) z += __expf(vals[k] - mx);
    }
#pragma unroll
    for (int o = 16; o; o >>= 1) z += __shfl_xor_sync(FULLW, z, o);
    if (lane == 0) sz[rloc][sub] = z;
    __syncthreads();
    float inv = 1.f / (sz[rloc][0] + sz[rloc][1]);

    float4 entry = make_float4(s1, mx, inv, __int_as_float(row));
#pragma unroll
    for (int k = 0; k < 3; k++) {
        int j = sub * 96 + k * 32 + lane;
        if (j < c) {
            int col = cols[k];
            int pc = atomicAdd(&g_colcnt[col], 1);
            if (pc < MAXD) g_collist4[(size_t)col * MAXD + pc] = entry;
        }
    }
}

// ---- shared gather epilogue: warp-level fp16 gather over edge list in smem ----
__device__ __forceinline__ void gather_store(const float* scoef, const int* scol, int c,
                                             int wid, int lane, int tid, int base, int part,
                                             float (*sres)[EE], float* out) {
    const __half2* y2 = reinterpret_cast<const __half2*>(g_yth);
    float2 a0 = {0.f, 0.f}, a1 = {0.f, 0.f}, a2 = {0.f, 0.f}, a3 = {0.f, 0.f};
    int j = 0;
    for (; j + 4 <= c; j += 4) {
        float c0 = scoef[j + 0]; int l0 = scol[j + 0];
        float c1 = scoef[j + 1]; int l1 = scol[j + 1];
        float c2 = scoef[j + 2]; int l2 = scol[j + 2];
        float c3 = scoef[j + 3]; int l3 = scol[j + 3];
        float2 v0 = __half22float2(__ldg(y2 + (size_t)l0 * 32 + lane));
        float2 v1 = __half22float2(__ldg(y2 + (size_t)l1 * 32 + lane));
        float2 v2 = __half22float2(__ldg(y2 + (size_t)l2 * 32 + lane));
        float2 v3 = __half22float2(__ldg(y2 + (size_t)l3 * 32 + lane));
        a0.x += c0 * v0.x; a0.y += c0 * v0.y;
        a1.x += c1 * v1.x; a1.y += c1 * v1.y;
        a2.x += c2 * v2.x; a2.y += c2 * v2.y;
        a3.x += c3 * v3.x; a3.y += c3 * v3.y;
    }
    for (; j < c; j++) {
        float cf = scoef[j];
        float2 v = __half22float2(__ldg(y2 + (size_t)scol[j] * 32 + lane));
        a0.x += cf * v.x; a0.y += cf * v.y;
    }
    a0.x += a1.x + a2.x + a3.x;
    a0.y += a1.y + a2.y + a3.y;
    sres[wid][2 * lane] = a0.x;
    sres[wid][2 * lane + 1] = a0.y;
    __syncthreads();

    for (int i = tid; i < 8 * EE; i += 256) {
        int e = i >> 3;
        int r = i & 7;
        out[(size_t)(part * EE + e) * NN + base + r] = sres[r][e];
    }
}

// ---- A3: fwd+geo aggregation (fused row softmax), warp per row ----
__global__ void aggE_fg_kernel(float* __restrict__ out) {
    int aa = (blockIdx.y == 0) ? 0 : 2;
    int base = blockIdx.x * 8;
    int tid = threadIdx.x;                // 256
    int wid = tid >> 5, lane = tid & 31;
    int row = base + wid;

    __shared__ float scoef[8][MAXD];
    __shared__ int   scol[8][MAXD];
    __shared__ float sres[8][EE];

    int c = g_cnt[aa][row];
    const int* list = &g_rowlist[aa][(size_t)row * MAXD];

    float s1 = g_sv[2 * aa][row];
    const float* s2 = g_s2[aa];
    float vals[MAXD / 32];
    int cols[MAXD / 32];
    float mx = -3.0e38f;
#pragma unroll
    for (int k = 0; k < MAXD / 32; k++) {
        int j = lane + k * 32;
        if (j < c) {
            int col = list[j];
            cols[k] = col;
            float x = lrelu(s1 + s2[col]);
            vals[k] = x;
            mx = fmaxf(mx, x);
        } else vals[k] = -3.0e38f;
    }
#pragma unroll
    for (int o = 16; o; o >>= 1) mx = fmaxf(mx, __shfl_xor_sync(FULLW, mx, o));
    float z = 0.f;
#pragma unroll
    for (int k = 0; k < MAXD / 32; k++) {
        int j = lane + k * 32;
        if (j < c) { float e = __expf(vals[k] - mx); vals[k] = e; z += e; }
    }
#pragma unroll
    for (int o = 16; o; o >>= 1) z += __shfl_xor_sync(FULLW, z, o);
    float inv = 1.f / z;
#pragma unroll
    for (int k = 0; k < MAXD / 32; k++) {
        int j = lane + k * 32;
        if (j < c) { scoef[wid][j] = vals[k] * inv; scol[wid][j] = cols[k]; }
    }
    __syncwarp();

    gather_store(scoef[wid], scol[wid], c, wid, lane, tid, base, aa + 1, sres, out);
}

// ---- B1: bwd aggregation — coalesced CSC float4 entries ----
__global__ void aggE_bwd_kernel(float* __restrict__ out) {
    int base = blockIdx.x * 8;
    int tid = threadIdx.x;                // 256
    int wid = tid >> 5, lane = tid & 31;
    int row = base + wid;

    __shared__ float scoef[8][MAXD];
    __shared__ int   scol[8][MAXD];
    __shared__ float sres[8][EE];

    int c = min(g_colcnt[row], MAXD);
    const float4* list = &g_collist4[(size_t)row * MAXD];
    float s2r = g_s2[1][row];
#pragma unroll
    for (int k = 0; k < MAXD / 32; k++) {
        int j = lane + k * 32;
        if (j < c) {
            float4 p = __ldg(list + j);     // coalesced within the warp
            float x = lrelu(p.x + s2r);
            scoef[wid][j] = __expf(x - p.y) * p.z;
            scol[wid][j] = __float_as_int(p.w);
        }
    }
    __syncwarp();

    gather_store(scoef[wid], scol[wid], c, wid, lane, tid, base, 2, sres, out);
}

extern "C" void kernel_launch(void* const* d_in, const int* in_sizes, int n_in,
                              void* d_out, int out_size) {
    const float* feat   = (const float*)d_in[0];
    const float* geo    = (const float*)d_in[1];
    const float* fwd    = (const float*)d_in[2];
    const float* bwd    = (const float*)d_in[3];
    const float* weight = (const float*)d_in[4];
    const float* Wf  = (const float*)d_in[5];
    const float* af1 = (const float*)d_in[6];
    const float* af2 = (const float*)d_in[7];
    const float* Wb  = (const float*)d_in[8];
    const float* ab1 = (const float*)d_in[9];
    const float* ab2 = (const float*)d_in[10];
    const float* Wg  = (const float*)d_in[11];
    const float* ag1 = (const float*)d_in[12];
    const float* ag2 = (const float*)d_in[13];
    float* out = (float*)d_out;

    static cudaStream_t sB = [] { cudaStream_t s; cudaStreamCreateWithFlags(&s, cudaStreamNonBlocking); return s; }();
    static cudaStream_t sC = [] { cudaStream_t s; cudaStreamCreateWithFlags(&s, cudaStreamNonBlocking); return s; }();
    static cudaEvent_t evRoot = [] { cudaEvent_t e; cudaEventCreateWithFlags(&e, cudaEventDisableTiming); return e; }();
    static cudaEvent_t evY    = [] { cudaEvent_t e; cudaEventCreateWithFlags(&e, cudaEventDisableTiming); return e; }();
    static cudaEvent_t evScan = [] { cudaEvent_t e; cudaEventCreateWithFlags(&e, cudaEventDisableTiming); return e; }();
    static cudaEvent_t evB    = [] { cudaEvent_t e; cudaEventCreateWithFlags(&e, cudaEventDisableTiming); return e; }();

    // fork streams off the main (captured) stream
    cudaEventRecord(evRoot, 0);
    cudaStreamWaitEvent(sC, evRoot, 0);
    cudaStreamWaitEvent(sB, evRoot, 0);

    // stream C: y (independent; hidden under scan)
    y_kernel<<<NN / 32, dim3(32, 8), 0, sC>>>(feat, weight, out);
    cudaEventRecord(evY, sC);

    // stream B: colcnt zero (hides under scan; csc_stats on sB follows it)
    zero_colcnt_kernel<<<NN / 256, 256, 0, sB>>>();

    // main stream: wa -> proj -> scan
    wa_kernel<<<1, 128>>>(Wf, af1, af2, Wb, ab1, ab2, Wg, ag1, ag2);
    proj_sv_kernel<<<NN / 8, 256>>>(feat);
    scan_kernel<<<dim3(NN, 3), 128>>>(fwd, bwd, geo);
    cudaEventRecord(evScan, 0);

    // stream B: csc_stats (after zero, after scan) -> aggE_bwd (needs y too)
    cudaStreamWaitEvent(sB, evScan, 0);
    csc_stats_kernel<<<NN / 4, 256, 0, sB>>>();
    cudaStreamWaitEvent(sB, evY, 0);
    aggE_bwd_kernel<<<NN / 8, 256, 0, sB>>>(out);
    cudaEventRecord(evB, sB);

    // main: fwd+geo aggregation (needs scan + y)
    cudaStreamWaitEvent(0, evY, 0);
    aggE_fg_kernel<<<dim3(NN / 8, 2), 256>>>(out);

    // join
    cudaStreamWaitEvent(0, evB, 0);
}

// round 17
// speedup vs baseline: 1.0494x; 1.0494x over previous
#include <cuda_runtime.h>
#include <cuda_fp16.h>

#define NN 4096
#define FF 128
#define EE 64
#define MAXD 192
#define LRALPHA 0.2f
#define FULLW 0xffffffffu

// ---- scratch (device globals) ----
__device__ float  g_wa[6][FF];
__device__ float  g_sv[6][NN];          // s1_fwd, u_fwd, s1_bwd, u_bwd, s1_geo, u_geo
__device__ float  g_s2[3][NN];
__device__ int    g_cnt[3][NN];
__device__ int    g_rowlist[3][NN * MAXD];
__device__ int    g_colcnt[NN];
__device__ float4 g_collist4[NN * MAXD]; // CSC entries: {s1_i, m_i, 1/Z_i, bitcast(i)}
__device__ __half g_yth[NN * EE];        // fp16 copy of (weight @ t^T), [n][e]

__device__ __forceinline__ float lrelu(float x) {
    return x > 0.f ? x : LRALPHA * x;
}

// ---- A0: blocks 0..15 zero colcnt; block 16 computes wa[k] = W @ a (R14 exact) ----
__global__ void init_kernel(const float* __restrict__ Wf, const float* __restrict__ af1, const float* __restrict__ af2,
                            const float* __restrict__ Wb, const float* __restrict__ ab1, const float* __restrict__ ab2,
                            const float* __restrict__ Wg, const float* __restrict__ ag1, const float* __restrict__ ag2) {
    int tid = threadIdx.x;            // 256
    if (blockIdx.x < 16) {
        g_colcnt[blockIdx.x * 256 + tid] = 0;
        return;
    }
    for (int i = tid; i < 6 * FF; i += 256) {
        int k = i >> 7;
        int f = i & 127;
        const float* W = (k < 2) ? Wf : (k < 4) ? Wb : Wg;
        const float* a = (k == 0) ? af1 : (k == 1) ? af2 : (k == 2) ? ab1 :
                         (k == 3) ? ab2 : (k == 4) ? ag1 : ag2;
        float s = 0.f;
#pragma unroll
        for (int e = 0; e < EE; e++) s += W[f * EE + e] * a[e];
        g_wa[k][f] = s;
    }
}

// ---- half-projection: computes sv[2j+KOFF][n] for j=0..2; warp per row ----
template <int KOFF>
__global__ void proj_half_kernel(const float* __restrict__ t) {
    __shared__ float swa[3][FF];
    int tid = threadIdx.x;            // 256
    for (int i = tid; i < 3 * FF; i += 256) {
        int j = i >> 7;
        int f = i & 127;
        swa[j][f] = g_wa[2 * j + KOFF][f];
    }
    __syncthreads();
    int wid = tid >> 5, lane = tid & 31;
    int row = blockIdx.x * 8 + wid;
    const float4* t4 = reinterpret_cast<const float4*>(t + (size_t)row * FF);
    float4 v = __ldg(t4 + lane);
    float acc[3];
#pragma unroll
    for (int j = 0; j < 3; j++) {
        float4 w = reinterpret_cast<const float4*>(swa[j])[lane];
        acc[j] = v.x * w.x + v.y * w.y + v.z * w.z + v.w * w.w;
    }
#pragma unroll
    for (int o = 16; o; o >>= 1) {
#pragma unroll
        for (int j = 0; j < 3; j++)
            acc[j] += __shfl_xor_sync(FULLW, acc[j], o);
    }
    if (lane == 0) {
#pragma unroll
        for (int j = 0; j < 3; j++) g_sv[2 * j + KOFF][row] = acc[j];
    }
}

// ---- C0: y = weight @ t^T -> out part 0 + fp16 table (R14 exact) ----
__global__ void y_kernel(const float* __restrict__ t,
                         const float* __restrict__ weight,
                         float* __restrict__ out) {
    int n0 = blockIdx.x * 32;
    __shared__ float Gs[FF][32];
    __shared__ float Ws[EE][FF];
    __shared__ __align__(16) __half Hs[32][EE];

    int tid = threadIdx.y * 32 + threadIdx.x;   // 256
    for (int i = tid; i < 32 * FF; i += 256) {
        int nn = i & 31;
        int f = i >> 5;
        Gs[f][nn] = t[(size_t)(n0 + nn) * FF + f];
    }
    for (int i = tid; i < EE * FF; i += 256)
        Ws[i / FF][i % FF] = weight[i];
    __syncthreads();

    int tx = threadIdx.x;
    int ty = threadIdx.y;
    float acc[8] = {0.f, 0.f, 0.f, 0.f, 0.f, 0.f, 0.f, 0.f};
    for (int f = 0; f < FF; f++) {
        float gv = Gs[f][tx];
#pragma unroll
        for (int eg = 0; eg < 8; eg++)
            acc[eg] += Ws[ty * 8 + eg][f] * gv;
    }
#pragma unroll
    for (int eg = 0; eg < 8; eg++) {
        int e = ty * 8 + eg;
        out[(size_t)e * NN + n0 + tx] = acc[eg];
        Hs[tx][e] = __float2half_rn(acc[eg]);
    }
    __syncthreads();
    {
        int nn = tid >> 3;
        int ch = tid & 7;
        reinterpret_cast<uint4*>(&g_yth[(size_t)(n0 + nn) * EE])[ch] =
            reinterpret_cast<const uint4*>(Hs[nn])[ch];
    }
}

// ---- A2: adjacency scan with inline dot. 128 thr/row, 8 uint4, __ldcs. ----
__global__ void scan_kernel(const float* __restrict__ fwd,
                            const float* __restrict__ bwd,
                            const float* __restrict__ geo) {
    int a = blockIdx.y;
    int row = blockIdx.x;
    const float* adj = (a == 0) ? fwd : (a == 1) ? bwd : geo;
    const uint4* rp = reinterpret_cast<const uint4*>(adj + (size_t)row * NN);

    __shared__ int scnt;
    __shared__ float sdot;
    if (threadIdx.x == 0) { scnt = 0; sdot = 0.f; }
    __syncthreads();

    const float* u = g_sv[2 * a + 1];
    int* list = &g_rowlist[a][(size_t)row * MAXD];
    int t = threadIdx.x;              // 0..127
    int lane = t & 31;

    uint4 v[8];
#pragma unroll
    for (int k = 0; k < 8; k++) v[k] = __ldcs(rp + t + k * 128);   // evict-first

    // 1.0f = 0x3F800000 -> (>>29)&1 == 1 ; 0.0f -> 0
    unsigned mask = 0;
#pragma unroll
    for (int k = 0; k < 8; k++) {
        mask |= ((v[k].x >> 29) & 1u) << (4 * k + 0);
        mask |= ((v[k].y >> 29) & 1u) << (4 * k + 1);
        mask |= ((v[k].z >> 29) & 1u) << (4 * k + 2);
        mask |= ((v[k].w >> 29) & 1u) << (4 * k + 3);
    }

    int cnt = __popc(mask);
    int incl = cnt;
#pragma unroll
    for (int d = 1; d < 32; d <<= 1) {
        int nb = __shfl_up_sync(FULLW, incl, d);
        if (lane >= d) incl += nb;
    }
    int warpTotal = __shfl_sync(FULLW, incl, 31);
    int excl = incl - cnt;
    int wb = 0;
    if (lane == 0 && warpTotal) wb = atomicAdd(&scnt, warpTotal);
    wb = __shfl_sync(FULLW, wb, 0);
    int base = wb + excl;

    float dot = 0.f;
    unsigned m = mask;
    while (m) {
        int b = __ffs(m) - 1;
        m &= m - 1;
        int col = (t << 2) + ((b >> 2) << 9) + (b & 3);
        if (base < MAXD) list[base] = col;
        base++;
        dot += u[col];
    }

#pragma unroll
    for (int o = 16; o; o >>= 1) dot += __shfl_xor_sync(FULLW, dot, o);
    if (lane == 0) atomicAdd(&sdot, dot);
    __syncthreads();

    if (threadIdx.x == 0) {
        int c = scnt;
        g_cnt[a][row] = min(c, MAXD);
        float deg = (c < 1) ? 1.f : (float)c;
        g_s2[a][row] = sdot / deg;
    }
}

// ---- B0: fused bwd softmax stats + CSC scatter — 2 warps per row (R14 exact) ----
__global__ void csc_stats_kernel() {
    int tid = threadIdx.x;            // 256
    int wid = tid >> 5, lane = tid & 31;
    int rloc = wid >> 1;
    int sub = wid & 1;
    int row = blockIdx.x * 4 + rloc;

    __shared__ float sm[4][2];
    __shared__ float sz[4][2];

    int c = g_cnt[1][row];
    const int* list = &g_rowlist[1][(size_t)row * MAXD];
    float s1 = g_sv[2][row];
    const float* s2 = g_s2[1];

    float vals[3];
    int cols[3];
    float mx = -3.0e38f;
#pragma unroll
    for (int k = 0; k < 3; k++) {
        int j = sub * 96 + k * 32 + lane;
        if (j < c) {
            int col = list[j];
            cols[k] = col;
            float x = lrelu(s1 + s2[col]);
            vals[k] = x;
            mx = fmaxf(mx, x);
        } else vals[k] = -3.0e38f;
    }
#pragma unroll
    for (int o = 16; o; o >>= 1) mx = fmaxf(mx, __shfl_xor_sync(FULLW, mx, o));
    if (lane == 0) sm[rloc][sub] = mx;
    __syncthreads();
    mx = fmaxf(sm[rloc][0], sm[rloc][1]);

    float z = 0.f;
#pragma unroll
    for (int k = 0; k < 3; k++) {
        int j = sub * 96 + k * 32 + lane;
        if (j < c) z += __expf(vals[k] - mx);
    }
#pragma unroll
    for (int o = 16; o; o >>= 1) z += __shfl_xor_sync(FULLW, z, o);
    if (lane == 0) sz[rloc][sub] = z;
    __syncthreads();
    float inv = 1.f / (sz[rloc][0] + sz[rloc][1]);

    float4 entry = make_float4(s1, mx, inv, __int_as_float(row));
#pragma unroll
    for (int k = 0; k < 3; k++) {
        int j = sub * 96 + k * 32 + lane;
        if (j < c) {
            int col = cols[k];
            int pc = atomicAdd(&g_colcnt[col], 1);
            if (pc < MAXD) g_collist4[(size_t)col * MAXD + pc] = entry;
        }
    }
}

// ---- shared gather epilogue: warp-level fp16 gather over edge list in smem ----
__device__ __forceinline__ void gather_store(const float* scoef, const int* scol, int c,
                                             int wid, int lane, int tid, int base, int part,
                                             float (*sres)[EE], float* out) {
    const __half2* y2 = reinterpret_cast<const __half2*>(g_yth);
    float2 a0 = {0.f, 0.f}, a1 = {0.f, 0.f}, a2 = {0.f, 0.f}, a3 = {0.f, 0.f};
    int j = 0;
    for (; j + 4 <= c; j += 4) {
        float c0 = scoef[j + 0]; int l0 = scol[j + 0];
        float c1 = scoef[j + 1]; int l1 = scol[j + 1];
        float c2 = scoef[j + 2]; int l2 = scol[j + 2];
        float c3 = scoef[j + 3]; int l3 = scol[j + 3];
        float2 v0 = __half22float2(__ldg(y2 + (size_t)l0 * 32 + lane));
        float2 v1 = __half22float2(__ldg(y2 + (size_t)l1 * 32 + lane));
        float2 v2 = __half22float2(__ldg(y2 + (size_t)l2 * 32 + lane));
        float2 v3 = __half22float2(__ldg(y2 + (size_t)l3 * 32 + lane));
        a0.x += c0 * v0.x; a0.y += c0 * v0.y;
        a1.x += c1 * v1.x; a1.y += c1 * v1.y;
        a2.x += c2 * v2.x; a2.y += c2 * v2.y;
        a3.x += c3 * v3.x; a3.y += c3 * v3.y;
    }
    for (; j < c; j++) {
        float cf = scoef[j];
        float2 v = __half22float2(__ldg(y2 + (size_t)scol[j] * 32 + lane));
        a0.x += cf * v.x; a0.y += cf * v.y;
    }
    a0.x += a1.x + a2.x + a3.x;
    a0.y += a1.y + a2.y + a3.y;
    sres[wid][2 * lane] = a0.x;
    sres[wid][2 * lane + 1] = a0.y;
    __syncthreads();

    for (int i = tid; i < 8 * EE; i += 256) {
        int e = i >> 3;
        int r = i & 7;
        out[(size_t)(part * EE + e) * NN + base + r] = sres[r][e];
    }
}

// ---- A3: fwd+geo aggregation (fused row softmax), warp per row (R14 exact) ----
__global__ void aggE_fg_kernel(float* __restrict__ out) {
    int aa = (blockIdx.y == 0) ? 0 : 2;
    int base = blockIdx.x * 8;
    int tid = threadIdx.x;                // 256
    int wid = tid >> 5, lane = tid & 31;
    int row = base + wid;

    __shared__ float scoef[8][MAXD];
    __shared__ int   scol[8][MAXD];
    __shared__ float sres[8][EE];

    int c = g_cnt[aa][row];
    const int* list = &g_rowlist[aa][(size_t)row * MAXD];

    float s1 = g_sv[2 * aa][row];
    const float* s2 = g_s2[aa];
    float vals[MAXD / 32];
    int cols[MAXD / 32];
    float mx = -3.0e38f;
#pragma unroll
    for (int k = 0; k < MAXD / 32; k++) {
        int j = lane + k * 32;
        if (j < c) {
            int col = list[j];
            cols[k] = col;
            float x = lrelu(s1 + s2[col]);
            vals[k] = x;
            mx = fmaxf(mx, x);
        } else vals[k] = -3.0e38f;
    }
#pragma unroll
    for (int o = 16; o; o >>= 1) mx = fmaxf(mx, __shfl_xor_sync(FULLW, mx, o));
    float z = 0.f;
#pragma unroll
    for (int k = 0; k < MAXD / 32; k++) {
        int j = lane + k * 32;
        if (j < c) { float e = __expf(vals[k] - mx); vals[k] = e; z += e; }
    }
#pragma unroll
    for (int o = 16; o; o >>= 1) z += __shfl_xor_sync(FULLW, z, o);
    float inv = 1.f / z;
#pragma unroll
    for (int k = 0; k < MAXD / 32; k++) {
        int j = lane + k * 32;
        if (j < c) { scoef[wid][j] = vals[k] * inv; scol[wid][j] = cols[k]; }
    }
    __syncwarp();

    gather_store(scoef[wid], scol[wid], c, wid, lane, tid, base, aa + 1, sres, out);
}

// ---- B1: bwd aggregation — coalesced CSC float4 entries (R14 exact) ----
__global__ void aggE_bwd_kernel(float* __restrict__ out) {
    int base = blockIdx.x * 8;
    int tid = threadIdx.x;                // 256
    int wid = tid >> 5, lane = tid & 31;
    int row = base + wid;

    __shared__ float scoef[8][MAXD];
    __shared__ int   scol[8][MAXD];
    __shared__ float sres[8][EE];

    int c = min(g_colcnt[row], MAXD);
    const float4* list = &g_collist4[(size_t)row * MAXD];
    float s2r = g_s2[1][row];
#pragma unroll
    for (int k = 0; k < MAXD / 32; k++) {
        int j = lane + k * 32;
        if (j < c) {
            float4 p = __ldg(list + j);     // coalesced within the warp
            float x = lrelu(p.x + s2r);
            scoef[wid][j] = __expf(x - p.y) * p.z;
            scol[wid][j] = __float_as_int(p.w);
        }
    }
    __syncwarp();

    gather_store(scoef[wid], scol[wid], c, wid, lane, tid, base, 2, sres, out);
}

extern "C" void kernel_launch(void* const* d_in, const int* in_sizes, int n_in,
                              void* d_out, int out_size) {
    const float* feat   = (const float*)d_in[0];
    const float* geo    = (const float*)d_in[1];
    const float* fwd    = (const float*)d_in[2];
    const float* bwd    = (const float*)d_in[3];
    const float* weight = (const float*)d_in[4];
    const float* Wf  = (const float*)d_in[5];
    const float* af1 = (const float*)d_in[6];
    const float* af2 = (const float*)d_in[7];
    const float* Wb  = (const float*)d_in[8];
    const float* ab1 = (const float*)d_in[9];
    const float* ab2 = (const float*)d_in[10];
    const float* Wg  = (const float*)d_in[11];
    const float* ag1 = (const float*)d_in[12];
    const float* ag2 = (const float*)d_in[13];
    float* out = (float*)d_out;

    static cudaStream_t sB = [] { cudaStream_t s; cudaStreamCreateWithFlags(&s, cudaStreamNonBlocking); return s; }();
    static cudaStream_t sC = [] { cudaStream_t s; cudaStreamCreateWithFlags(&s, cudaStreamNonBlocking); return s; }();
    static cudaEvent_t evRoot = [] { cudaEvent_t e; cudaEventCreateWithFlags(&e, cudaEventDisableTiming); return e; }();
    static cudaEvent_t evInit = [] { cudaEvent_t e; cudaEventCreateWithFlags(&e, cudaEventDisableTiming); return e; }();
    static cudaEvent_t evC    = [] { cudaEvent_t e; cudaEventCreateWithFlags(&e, cudaEventDisableTiming); return e; }();
    static cudaEvent_t evScan = [] { cudaEvent_t e; cudaEventCreateWithFlags(&e, cudaEventDisableTiming); return e; }();
    static cudaEvent_t evB    = [] { cudaEvent_t e; cudaEventCreateWithFlags(&e, cudaEventDisableTiming); return e; }();

    // fork stream C off the main (captured) stream
    cudaEventRecord(evRoot, 0);
    cudaStreamWaitEvent(sC, evRoot, 0);

    // main stream: init (zero colcnt + wa) -> proj_u (scan's dot input only) -> scan
    init_kernel<<<17, 256>>>(Wf, af1, af2, Wb, ab1, ab2, Wg, ag1, ag2);
    cudaEventRecord(evInit, 0);
    proj_half_kernel<1><<<NN / 8, 256>>>(feat);   // u vectors (k = 1,3,5)
    scan_kernel<<<dim3(NN, 3), 128>>>(fwd, bwd, geo);
    cudaEventRecord(evScan, 0);

    // stream C: y, then s1 projection (needs wa via evInit) — hidden under scan
    y_kernel<<<NN / 32, dim3(32, 8), 0, sC>>>(feat, weight, out);
    cudaStreamWaitEvent(sC, evInit, 0);
    proj_half_kernel<0><<<NN / 8, 256, 0, sC>>>(feat);  // s1 vectors (k = 0,2,4)
    cudaEventRecord(evC, sC);

    // stream B: csc_stats (needs scan + s1) -> aggE_bwd (y covered by evC)
    cudaStreamWaitEvent(sB, evScan, 0);
    cudaStreamWaitEvent(sB, evC, 0);
    csc_stats_kernel<<<NN / 4, 256, 0, sB>>>();
    aggE_bwd_kernel<<<NN / 8, 256, 0, sB>>>(out);
    cudaEventRecord(evB, sB);

    // main: fwd+geo aggregation (needs scan + y + s1)
    cudaStreamWaitEvent(0, evC, 0);
    aggE_fg_kernel<<<dim3(NN / 8, 2), 256>>>(out);

    // join
    cudaStreamWaitEvent(0, evB, 0);
}